// round 5
// baseline (speedup 1.0000x reference)
#include <cuda_runtime.h>

#define NN 32
#define CC 256
#define SS 30
#define HWD 256        // 16*16 pixels per frame
#define PP 16          // parts
#define CT 16          // channels per tile
#define PIT 260        // pitch: 16B-aligned rows, 2-way worst-case LDS
#define TILES 4        // tiles per block (block covers 64 channels)

__device__ int g_lab64;

// Detect label dtype layout: int64 little-endian -> odd 32-bit words all 0.
__global__ void detect_label_dtype(const int* __restrict__ lab)
{
    if (threadIdx.x == 0) {
        int any = 0;
        #pragma unroll 8
        for (int i = 1; i < 256; i += 2) any |= lab[i];
        g_lab64 = (any == 0) ? 1 : 0;
    }
}

#define CP_ASYNC16(dst, src) \
    asm volatile("cp.async.cg.shared.global [%0], [%1], 16;" :: "r"(dst), "l"(src) : "memory")
#define CP_COMMIT() asm volatile("cp.async.commit_group;" ::: "memory")
#define CP_WAIT(n)  asm volatile("cp.async.wait_group %0;" :: "n"(n) : "memory")

// order-preserving float<->uint encoding for atomicMax
__device__ __forceinline__ unsigned fenc(float f) {
    unsigned b = __float_as_uint(f);
    return (b & 0x80000000u) ? ~b : (b | 0x80000000u);
}
__device__ __forceinline__ float fdec(unsigned v) {
    return __uint_as_float((v & 0x80000000u) ? (v ^ 0x80000000u) : ~v);
}

__global__ __launch_bounds__(256, 6)
void part_pool_kernel(const float* __restrict__ x,
                      const void* __restrict__ labels_raw,
                      float* __restrict__ out)
{
    extern __shared__ float tiles[];          // 2 * CT*PIT floats = 33,280 B
    __shared__ float          psum[PP * 17];  // 1088 B  (pad 17: conflict-free finalize)
    __shared__ unsigned       pmax[PP * 17];  // 1088 B
    __shared__ unsigned short pk[HWD];        //  512 B  (label<<8 | pixel, part-sorted)
    __shared__ int cnt[PP], off[PP], fill[PP];

    const int bid = blockIdx.x;               // 0..3839
    const int f   = bid >> 2;                 // frame
    const int q   = bid & 3;                  // channel quarter (64 channels)
    const int n = f / SS;
    const int s = f % SS;
    const int t = threadIdx.x;

    // ---- per-frame label bucketing -> part-sorted pixel list ----
    if (t < PP) { cnt[t] = 0; fill[t] = 0; }
    __syncthreads();

    int myl;
    if (g_lab64) myl = (int)((const long long*)labels_raw)[(size_t)f * HWD + t];
    else         myl = ((const int*)labels_raw)[(size_t)f * HWD + t];
    myl &= (PP - 1);
    atomicAdd(&cnt[myl], 1);
    __syncthreads();

    if (t == 0) {
        int acc = 0;
        #pragma unroll
        for (int p = 0; p < PP; p++) { off[p] = acc; acc += cnt[p]; }
    }
    __syncthreads();
    pk[off[myl] + atomicAdd(&fill[myl], 1)] = (unsigned short)((myl << 8) | t);

    // init pooled accumulators (ordered before first compute by tile-ready sync)
    {
        int i = t;                            // 256 threads cover 272 slots in 2 steps
        psum[i] = 0.0f; pmax[i] = 0u;
        i += 256;
        if (i < PP * 17) { psum[i] = 0.0f; pmax[i] = 0u; }
    }

    const float* xf = x + ((size_t)(n * CC + q * (TILES * CT)) * SS + s) * HWD;
    const unsigned stile = (unsigned)__cvta_generic_to_shared(tiles);

    // 16B cp.async: thread t loads channel t>>4, 4 groups of 4 pixels (coalesced)
    const int lcl = t >> 4;
    const int lg  = t & 15;
    #define LOAD_TILE(tt, buf) do {                                            \
        const float* _row = xf + (size_t)((tt) * CT + lcl) * (SS * HWD);       \
        unsigned _dst = stile + (unsigned)(((buf) * CT + lcl) * (PIT * 4));    \
        _Pragma("unroll")                                                      \
        for (int _k = 0; _k < 4; _k++) {                                       \
            int _g = lg + 16 * _k;                                             \
            CP_ASYNC16(_dst + _g * 16, _row + _g * 4);                         \
        }                                                                      \
        CP_COMMIT();                                                           \
    } while (0)

    // balanced compute roles: half-warp g owns sorted positions [16g,16g+16),
    // lane&15 = channel. Fixed 16-iteration trip count, zero imbalance.
    const int g  = t >> 4;                    // range group 0..15 (= half-warp)
    const int cl = t & 15;                    // channel-in-tile

    LOAD_TILE(0, 0);

    for (int tt = 0; tt < TILES; tt++) {
        const int buf = tt & 1;
        if (tt + 1 < TILES) { LOAD_TILE(tt + 1, buf ^ 1); CP_WAIT(1); }
        else                { CP_WAIT(0); }
        __syncthreads();          // tile tt ready; pooled (re)init complete

        const float* tb = tiles + (buf * CT + cl) * PIT;

        // walk 16 sorted pixels; flush each part-run via smem atomics
        {
            int   e0    = pk[g * 16];                 // broadcast LDS
            int   prevp = e0 >> 8;
            float v0    = tb[e0 & 255];
            float sum   = v0;
            float mx    = v0;
            #pragma unroll 5
            for (int j = 1; j < 16; j++) {
                int   e = pk[g * 16 + j];
                int   p = e >> 8;
                float v = tb[e & 255];
                if (p != prevp) {
                    atomicAdd(&psum[prevp * 17 + cl], sum);
                    atomicMax(&pmax[prevp * 17 + cl], fenc(mx));
                    prevp = p; sum = 0.0f; mx = -3.0e38f;
                }
                sum += v;
                mx = fmaxf(mx, v);
            }
            atomicAdd(&psum[prevp * 17 + cl], sum);
            atomicMax(&pmax[prevp * 17 + cl], fenc(mx));
        }
        __syncthreads();          // all atomics done

        // finalize + coalesced store: thread t -> (channel t>>4, part t&15)
        {
            int cc = t >> 4;
            int pp = t & 15;
            int cN = cnt[pp];
            float r = 0.0f;
            if (cN > 0)
                r = psum[pp * 17 + cc] / (float)cN
                  + fmaxf(fdec(pmax[pp * 17 + cc]), -100.0f);
            int c = q * (TILES * CT) + tt * CT + cc;
            out[((size_t)(n * CC + c) * SS + s) * PP + pp] = r;
        }
        __syncthreads();          // finalize reads done before re-init

        // re-init pooled for next tile (ordered before atomics by next
        // iteration's tile-ready __syncthreads)
        if (tt + 1 < TILES) {
            int i = t;
            psum[i] = 0.0f; pmax[i] = 0u;
            i += 256;
            if (i < PP * 17) { psum[i] = 0.0f; pmax[i] = 0u; }
        }
    }
    #undef LOAD_TILE
}

extern "C" void kernel_launch(void* const* d_in, const int* in_sizes, int n_in,
                              void* d_out, int out_size)
{
    const float* x      = (const float*)d_in[0];
    const void*  labels = d_in[1];
    float*       out    = (float*)d_out;

    cudaFuncSetAttribute(part_pool_kernel,
                         cudaFuncAttributeMaxDynamicSharedMemorySize,
                         2 * CT * PIT * 4);

    detect_label_dtype<<<1, 32>>>((const int*)labels);
    part_pool_kernel<<<NN * SS * 4, 256, 2 * CT * PIT * 4>>>(x, labels, out);
}

// round 6
// speedup vs baseline: 1.0065x; 1.0065x over previous
#include <cuda_runtime.h>

#define NN 32
#define CC 256
#define SS 30
#define HWD 256        // 16*16 pixels per frame
#define PP 16          // parts
#define CT 16          // channels per tile
#define PIT 260        // pitch: 16B-aligned rows, 2-way worst-case LDS
#define TILES 4        // tiles per block (block covers 64 channels)

__device__ int g_lab64;

// Detect label dtype layout: int64 little-endian -> odd 32-bit words all 0.
__global__ void detect_label_dtype(const int* __restrict__ lab)
{
    if (threadIdx.x == 0) {
        int any = 0;
        #pragma unroll 8
        for (int i = 1; i < 256; i += 2) any |= lab[i];
        g_lab64 = (any == 0) ? 1 : 0;
    }
}

#define CP_ASYNC16(dst, src) \
    asm volatile("cp.async.cg.shared.global [%0], [%1], 16;" :: "r"(dst), "l"(src) : "memory")
#define CP_COMMIT() asm volatile("cp.async.commit_group;" ::: "memory")
#define CP_WAIT(n)  asm volatile("cp.async.wait_group %0;" :: "n"(n) : "memory")

__global__ __launch_bounds__(256, 6)
void part_pool_kernel(const float* __restrict__ x,
                      const void* __restrict__ labels_raw,
                      float* __restrict__ out)
{
    extern __shared__ float tiles[];      // 2 * CT*PIT floats = 33,280 B
    __shared__ float pooled[CT * 17];
    __shared__ int   order[HWD + 48];     // padded: reg-preload reads o+47 safely
    __shared__ float rinv[PP];
    __shared__ int   cnt[PP], off[PP], fill[PP];

    const int bid = blockIdx.x;           // 0..3839
    const int f   = bid >> 2;             // frame
    const int q   = bid & 3;              // channel quarter (64 channels)
    const int n = f / SS;
    const int s = f % SS;
    const int t = threadIdx.x;
    const int w = t >> 5;
    const int l = t & 31;

    // ---- per-frame label bucketing ----
    if (t < PP) { cnt[t] = 0; fill[t] = 0; }
    if (t >= HWD - 48 + 256 - 48) {}      // (no-op)
    __syncthreads();

    int myl;
    if (g_lab64) myl = (int)((const long long*)labels_raw)[(size_t)f * HWD + t];
    else         myl = ((const int*)labels_raw)[(size_t)f * HWD + t];
    myl &= (PP - 1);
    atomicAdd(&cnt[myl], 1);
    // zero the padding region of order[] so preloads read defined values
    if (t < 48) order[HWD + t] = 0;
    __syncthreads();

    if (t == 0) {
        int acc = 0;
        #pragma unroll
        for (int p = 0; p < PP; p++) { off[p] = acc; acc += cnt[p]; }
    }
    if (t < PP) rinv[t] = (cnt[t] > 0) ? (1.0f / (float)cnt[t]) : 0.0f;
    __syncthreads();
    order[off[myl] + atomicAdd(&fill[myl], 1)] = t;
    __syncthreads();                      // order[] complete

    // per-lane fixed roles: half-warp owns one part, lane&15 = channel in tile
    const int p  = (w << 1) | (l >> 4);   // part 0..15
    const int cl = l & 15;                // channel-in-tile
    const int cN = cnt[p];
    const int o  = off[p];
    const float rc = rinv[p];
    const unsigned hmask = 0xFFFFu << (l & 16);   // own half-warp's lanes

    // register-cache the pixel list (lane j of half holds entries j, j+16, j+32)
    const int ord0 = order[o + (l & 15)];
    const int ord1 = order[o + (l & 15) + 16];
    const int ord2 = order[o + (l & 15) + 32];

    const float* xf = x + ((size_t)(n * CC + q * (TILES * CT)) * SS + s) * HWD;
    const unsigned stile = (unsigned)__cvta_generic_to_shared(tiles);

    // 16B cp.async: thread t loads channel t>>4, 4 groups of 4 pixels (coalesced)
    const int lcl = t >> 4;
    const int lg  = t & 15;
    #define LOAD_TILE(tt, buf) do {                                            \
        const float* _row = xf + (size_t)((tt) * CT + lcl) * (SS * HWD);       \
        unsigned _dst = stile + (unsigned)(((buf) * CT + lcl) * (PIT * 4));    \
        _Pragma("unroll")                                                      \
        for (int _k = 0; _k < 4; _k++) {                                       \
            int _g = lg + 16 * _k;                                             \
            CP_ASYNC16(_dst + _g * 16, _row + _g * 4);                         \
        }                                                                      \
        CP_COMMIT();                                                           \
    } while (0)

    LOAD_TILE(0, 0);

    for (int tt = 0; tt < TILES; tt++) {
        const int buf = tt & 1;
        if (tt + 1 < TILES) { LOAD_TILE(tt + 1, buf ^ 1); CP_WAIT(1); }
        else                { CP_WAIT(0); }
        __syncthreads();                  // tile tt visible to all

        const float* tb = tiles + (buf * CT + cl) * PIT;

        float sum = 0.0f;
        float mx  = -3.0e38f;
        {   // chunk 0: entries 0..15 via ord0
            int m = cN < 16 ? cN : 16;
            #pragma unroll 4
            for (int jj = 0; jj < m; jj++) {
                int pix = __shfl_sync(hmask, ord0, jj, 16);
                float v = tb[pix];
                sum += v; mx = fmaxf(mx, v);
            }
        }
        if (cN > 16) {                    // chunk 1: entries 16..31
            int m = cN - 16; if (m > 16) m = 16;
            #pragma unroll 4
            for (int jj = 0; jj < m; jj++) {
                int pix = __shfl_sync(hmask, ord1, jj, 16);
                float v = tb[pix];
                sum += v; mx = fmaxf(mx, v);
            }
        }
        if (cN > 32) {                    // chunk 2: entries 32..47
            int m = cN - 32; if (m > 16) m = 16;
            #pragma unroll 4
            for (int jj = 0; jj < m; jj++) {
                int pix = __shfl_sync(hmask, ord2, jj, 16);
                float v = tb[pix];
                sum += v; mx = fmaxf(mx, v);
            }
        }
        for (int j = 48; j < cN; j++) {   // astronomically rare tail
            float v = tb[order[o + j]];
            sum += v; mx = fmaxf(mx, v);
        }

        float r = 0.0f;
        if (cN > 0)
            r = sum * rc + fmaxf(mx, -100.0f);   // mean + amax(incl -100)
        pooled[cl * 17 + p] = r;

        __syncthreads();                  // pooled ready AND buffer reads done

        // coalesced store: thread t -> (channel t>>4, part t&15)
        {
            int cc = t >> 4;
            int pp = t & 15;
            int c  = q * (TILES * CT) + tt * CT + cc;
            out[((size_t)(n * CC + c) * SS + s) * PP + pp] = pooled[cc * 17 + pp];
        }
        // next iter's LOAD overwrites buf^1 (tile tt-1): its compute finished
        // before the sync above -> safe.
    }
    #undef LOAD_TILE
}

extern "C" void kernel_launch(void* const* d_in, const int* in_sizes, int n_in,
                              void* d_out, int out_size)
{
    const float* x      = (const float*)d_in[0];
    const void*  labels = d_in[1];
    float*       out    = (float*)d_out;

    cudaFuncSetAttribute(part_pool_kernel,
                         cudaFuncAttributeMaxDynamicSharedMemorySize,
                         2 * CT * PIT * 4);

    detect_label_dtype<<<1, 32>>>((const int*)labels);
    part_pool_kernel<<<NN * SS * 4, 256, 2 * CT * PIT * 4>>>(x, labels, out);
}

// round 7
// speedup vs baseline: 1.0240x; 1.0173x over previous
#include <cuda_runtime.h>

#define NN 32
#define CC 256
#define SS 30
#define HWD 256        // 16*16 pixels per frame
#define PP 16          // parts
#define CT 16          // channels per tile
#define PIT 260        // pitch: 16B-aligned rows, 2-way worst-case LDS
#define TILES 4        // tiles per block (block covers 64 channels)

__device__ int g_lab64;

// Detect label dtype layout: int64 little-endian -> odd 32-bit words all 0.
__global__ void detect_label_dtype(const int* __restrict__ lab)
{
    if (threadIdx.x == 0) {
        int any = 0;
        #pragma unroll 8
        for (int i = 1; i < 256; i += 2) any |= lab[i];
        g_lab64 = (any == 0) ? 1 : 0;
    }
}

#define CP_ASYNC16(dst, src) \
    asm volatile("cp.async.cg.shared.global [%0], [%1], 16;" :: "r"(dst), "l"(src) : "memory")
#define CP_COMMIT() asm volatile("cp.async.commit_group;" ::: "memory")
#define CP_WAIT(n)  asm volatile("cp.async.wait_group %0;" :: "n"(n) : "memory")

__global__ __launch_bounds__(256, 6)
void part_pool_kernel(const float* __restrict__ x,
                      const void* __restrict__ labels_raw,
                      float* __restrict__ out)
{
    extern __shared__ float tiles[];          // 2 * CT*PIT floats = 33,280 B
    __shared__ unsigned int pk4w[(HWD + PP * 4) / 4];  // byte pixel lists, 4-padded per part
    __shared__ float rinv[PP];
    __shared__ int cnt[PP], off4[PP], fill[PP];

    unsigned char* pk4 = (unsigned char*)pk4w;

    const int bid = blockIdx.x;               // 0..3839
    const int f   = bid >> 2;                 // frame
    const int q   = bid & 3;                  // channel quarter (64 channels)
    const int n = f / SS;
    const int s = f % SS;
    const int t = threadIdx.x;
    const int w = t >> 5;
    const int l = t & 31;

    // ---- per-frame label bucketing -> 4-padded per-part byte pixel lists ----
    if (t < PP) { cnt[t] = 0; fill[t] = 0; }
    __syncthreads();

    int myl;
    if (g_lab64) myl = (int)((const long long*)labels_raw)[(size_t)f * HWD + t];
    else         myl = ((const int*)labels_raw)[(size_t)f * HWD + t];
    myl &= (PP - 1);
    atomicAdd(&cnt[myl], 1);
    __syncthreads();

    if (t == 0) {
        int acc = 0;
        #pragma unroll
        for (int p = 0; p < PP; p++) { off4[p] = acc; acc += (cnt[p] + 3) & ~3; }
    }
    if (t < PP) rinv[t] = (cnt[t] > 0) ? (1.0f / (float)cnt[t]) : 0.0f;
    __syncthreads();
    pk4[off4[myl] + atomicAdd(&fill[myl], 1)] = (unsigned char)t;
    __syncthreads();
    // pad each part's list to a multiple of 4 with its first pixel
    if (t < PP && cnt[t] > 0) {
        int o = off4[t];
        unsigned char p0 = pk4[o];
        for (int k = cnt[t]; k & 3; k++) pk4[o + k] = p0;
    }
    __syncthreads();                          // lists complete

    // per-lane fixed roles: half-warp owns one part, lane&15 = channel in tile
    const int p  = (w << 1) | (l >> 4);       // part 0..15
    const int cl = l & 31 & 15;               // channel-in-tile
    const int cN = cnt[p];
    const int o4 = off4[p];
    const int kN = (cN + 3) >> 2;             // 4-pixel chunks
    const float rc = rinv[p];
    const unsigned int* mylist = pk4w + (o4 >> 2);

    const float* xf = x + ((size_t)(n * CC + q * (TILES * CT)) * SS + s) * HWD;
    const unsigned stile = (unsigned)__cvta_generic_to_shared(tiles);

    // 16B cp.async: thread t loads channel t>>4, 4 groups of 4 pixels (coalesced)
    const int lcl = t >> 4;
    const int lg  = t & 15;
    #define LOAD_TILE(tt, buf) do {                                            \
        const float* _row = xf + (size_t)((tt) * CT + lcl) * (SS * HWD);       \
        unsigned _dst = stile + (unsigned)(((buf) * CT + lcl) * (PIT * 4));    \
        _Pragma("unroll")                                                      \
        for (int _k = 0; _k < 4; _k++) {                                       \
            int _g = lg + 16 * _k;                                             \
            CP_ASYNC16(_dst + _g * 16, _row + _g * 4);                         \
        }                                                                      \
        CP_COMMIT();                                                           \
    } while (0)

    LOAD_TILE(0, 0);

    for (int tt = 0; tt < TILES; tt++) {
        const int buf = tt & 1;
        CP_WAIT(0);                           // tile tt landed
        __syncthreads();                      // all see tile tt; all done with buf^1
        if (tt + 1 < TILES) LOAD_TILE(tt + 1, buf ^ 1);   // overlaps compute

        const float* tb = tiles + (buf * CT + cl) * PIT;

        float sum = 0.0f;
        float mx  = -3.0e38f;
        #pragma unroll 2
        for (int k = 0; k < kN; k++) {
            unsigned u = mylist[k];           // broadcast LDS: 4 pixel ids
            float a = tb[u & 255u];
            float b = tb[(u >> 8) & 255u];
            float c = tb[(u >> 16) & 255u];
            float d = tb[u >> 24];
            sum += (a + b) + (c + d);
            mx = fmaxf(fmaxf(mx, fmaxf(a, b)), fmaxf(c, d));
        }

        float r = 0.0f;
        if (cN > 0) {
            int pad = (kN << 2) - cN;         // 0..3 duplicated first-pixel copies
            if (pad) sum -= (float)pad * tb[pk4[o4]];
            r = sum * rc + fmaxf(mx, -100.0f);   // mean + amax(incl -100 init)
        }

        // direct scattered store: thread owns (channel cl, part p) of this tile
        int c = q * (TILES * CT) + tt * CT + cl;
        out[((size_t)(n * CC + c) * SS + s) * PP + p] = r;
        // no trailing sync: next iteration's CP_WAIT+__syncthreads orders
        // buffer reuse for every warp.
    }
    #undef LOAD_TILE
}

extern "C" void kernel_launch(void* const* d_in, const int* in_sizes, int n_in,
                              void* d_out, int out_size)
{
    const float* x      = (const float*)d_in[0];
    const void*  labels = d_in[1];
    float*       out    = (float*)d_out;

    cudaFuncSetAttribute(part_pool_kernel,
                         cudaFuncAttributeMaxDynamicSharedMemorySize,
                         2 * CT * PIT * 4);

    detect_label_dtype<<<1, 32>>>((const int*)labels);
    part_pool_kernel<<<NN * SS * 4, 256, 2 * CT * PIT * 4>>>(x, labels, out);
}